// round 11
// baseline (speedup 1.0000x reference)
#include <cuda_runtime.h>
#include <cuda_fp16.h>
#include <cstdint>

#define MM 32
#define KK 8192
#define NN 28672
#define N_TILE 64
#define K_TILE 64
#define NK_ITERS (KK / K_TILE)            // 128
#define A_STRIDE 144                      // 64 halves (128B) + 16B pad
#define WP_STRIDE 144                     // 64 u16 k-pairs (128B) + 16B pad
#define A_BYTES (MM * A_STRIDE)           // 4608
#define W_BYTES ((K_TILE / 2) * WP_STRIDE)// 4608
#define STAGE_BYTES (A_BYTES + W_BYTES)   // 9216
#define SMEM_BYTES (2 * STAGE_BYTES)      // 18432

__device__ __half g_act16[MM * KK];       // 512KB static scratch (L2-resident)

__device__ __forceinline__ uint32_t prmt_(uint32_t a, uint32_t b, uint32_t s) {
    uint32_t d;
    asm("prmt.b32 %0,%1,%2,%3;" : "=r"(d) : "r"(a), "r"(b), "r"(s));
    return d;
}

// 4 int32 (each holding one int8 value) -> 4 packed bytes
__device__ __forceinline__ uint32_t pack4_(int4 v) {
    return prmt_(prmt_((uint32_t)v.x, (uint32_t)v.y, 0x0040u),
                 prmt_((uint32_t)v.z, (uint32_t)v.w, 0x0040u), 0x5410u);
}

// u16 with int8 bytes [b0,b1] -> half2 {fp16(b0), fp16(b1)}. Exact:
// flip sign (u=b+128), splice 0x64 exponent (1024+u), subtract 1152.
__device__ __forceinline__ uint32_t cvt_pair_h2(uint32_t x) {
    uint32_t p = x ^ 0x00008080u;
    uint32_t h = prmt_(p, 0x64646464u, 0x4140u);
    uint32_t magic = 0x64806480u;                 // half2(1152,1152)
    __half2 r = __hsub2(*reinterpret_cast<__half2*>(&h),
                        *reinterpret_cast<__half2*>(&magic));
    return *reinterpret_cast<uint32_t*>(&r);
}

__device__ __forceinline__ void mma16816(float* c, const uint32_t* a,
                                         uint32_t b0, uint32_t b1) {
    asm volatile(
        "mma.sync.aligned.m16n8k16.row.col.f32.f16.f16.f32 "
        "{%0,%1,%2,%3}, {%4,%5,%6,%7}, {%8,%9}, {%0,%1,%2,%3};"
        : "+f"(c[0]), "+f"(c[1]), "+f"(c[2]), "+f"(c[3])
        : "r"(a[0]), "r"(a[1]), "r"(a[2]), "r"(a[3]), "r"(b0), "r"(b1));
}

__device__ __forceinline__ void cp16(uint32_t dst_smem, const void* src) {
    asm volatile("cp.async.cg.shared.global [%0], [%1], 16;"
                 :: "r"(dst_smem), "l"(src));
}

// ---- pre-pass: act fp32 -> fp16 --------------------------------------------
__global__ void cvt_act_kernel(const float* __restrict__ act) {
    int i = blockIdx.x * blockDim.x + threadIdx.x;
    float2 v = ((const float2*)act)[i];
    ((__half2*)g_act16)[i] = __floats2half2_rn(v.x, v.y);
}

// ---- main GEMM -------------------------------------------------------------
__global__ void __launch_bounds__(256, 3)
i8w_gemm_f32(const int* __restrict__ w32,
             const float* __restrict__ scale,
             float* __restrict__ out) {
    extern __shared__ char smem[];
    const int tid  = threadIdx.x;
    const int warp = tid >> 5;
    const int lane = tid & 31;
    const int g  = lane >> 2;
    const int tg = lane & 3;
    const int n0 = blockIdx.x * N_TILE;
    const uint32_t smem_u = (uint32_t)__cvta_generic_to_shared(smem);

    // weight fetch: thread owns k-pair pr (rows 2pr,2pr+1), 8-n segment ns
    const int pr = tid >> 3;     // 0..31
    const int ns = tid & 7;      // 0..7

    float acc[2][4];
    #pragma unroll
    for (int mf = 0; mf < 2; mf++)
        #pragma unroll
        for (int r = 0; r < 4; r++) acc[mf][r] = 0.f;

    int4 rbA[4], rbB[4];         // chunk c lives in rb[c&1]

    auto fetchW = [&](int kt, int4* rb) {
        const int k0 = kt * K_TILE;
        const int4* se = (const int4*)(w32 + (size_t)(k0 + 2 * pr) * NN
                                       + n0 + ns * 8);
        const int4* so = (const int4*)(w32 + (size_t)(k0 + 2 * pr + 1) * NN
                                       + n0 + ns * 8);
        rb[0] = __ldg(se);
        rb[1] = __ldg(se + 1);
        rb[2] = __ldg(so);
        rb[3] = __ldg(so + 1);
    };

    // pack int32->int8, interleave (k,k+1) n-major, one STS.128
    auto stageW = [&](int s, const int4* rb) {
        uint32_t pe0 = pack4_(rb[0]), pe1 = pack4_(rb[1]);
        uint32_t po0 = pack4_(rb[2]), po1 = pack4_(rb[3]);
        uint4 u;
        u.x = prmt_(pe0, po0, 0x5140u);   // [e0,o0,e1,o1]
        u.y = prmt_(pe0, po0, 0x7362u);   // [e2,o2,e3,o3]
        u.z = prmt_(pe1, po1, 0x5140u);
        u.w = prmt_(pe1, po1, 0x7362u);
        *(uint4*)(smem + s * STAGE_BYTES + A_BYTES
                  + pr * WP_STRIDE + ns * 16) = u;
    };

    auto cpA = [&](int kt, int s) {
        const int row = tid >> 3, c8 = tid & 7;
        cp16(smem_u + s * STAGE_BYTES + row * A_STRIDE + c8 * 16,
             g_act16 + (size_t)row * KK + kt * K_TILE + c8 * 8);
        asm volatile("cp.async.commit_group;");
    };

    const int colb2 = (warp * 8 + g) * 2;   // byte offset of u16 in pair-row
    auto compute = [&](int s) {
        const uint32_t sA = smem_u + s * STAGE_BYTES;
        const char* Wp = smem + s * STAGE_BYTES + A_BYTES;
        #pragma unroll
        for (int k16 = 0; k16 < 4; k16++) {
            const int kb = k16 * 16;
            uint32_t a[2][4];
            #pragma unroll
            for (int mf = 0; mf < 2; mf++) {
                uint32_t addr = sA + (mf * 16 + (lane & 15)) * A_STRIDE
                              + kb * 2 + (lane >> 4) * 16;
                asm volatile(
                    "ldmatrix.sync.aligned.m8n8.x4.shared.b16 {%0,%1,%2,%3}, [%4];"
                    : "=r"(a[mf][0]), "=r"(a[mf][1]),
                      "=r"(a[mf][2]), "=r"(a[mf][3])
                    : "r"(addr));
            }
            const int prb = k16 * 8 + tg;
            uint32_t x0 = *(const unsigned short*)(Wp + prb * WP_STRIDE + colb2);
            uint32_t x1 = *(const unsigned short*)(Wp + (prb + 4) * WP_STRIDE + colb2);
            uint32_t b0 = cvt_pair_h2(x0);
            uint32_t b1 = cvt_pair_h2(x1);
            mma16816(acc[0], a[0], b0, b1);
            mma16816(acc[1], a[1], b0, b1);
        }
    };

    // ---- preamble --------------------------------------------------------
    fetchW(0, rbA);
    fetchW(1, rbB);
    stageW(0, rbA);
    cpA(0, 0);
    cpA(1, 1);
    asm volatile("cp.async.wait_group 1;");   // A(0) ready
    __syncthreads();

    // ---- mainloop: distance-2 W pipeline, 2 smem stages ------------------
    for (int kt = 0; kt < NK_ITERS; kt++) {
        int4* rb_fetch = (kt & 1) ? rbB : rbA;     // rb[(kt+2)&1] = rb[kt&1]
        int4* rb_stage = (kt & 1) ? rbA : rbB;     // rb[(kt+1)&1]
        if (kt + 2 < NK_ITERS) fetchW(kt + 2, rb_fetch);
        compute(kt & 1);
        __syncthreads();
        if (kt + 1 < NK_ITERS) {
            stageW((kt + 1) & 1, rb_stage);        // cover: 1 full iteration
            if (kt + 2 < NK_ITERS) {
                cpA(kt + 2, kt & 1);
                asm volatile("cp.async.wait_group 1;");
            } else {
                asm volatile("cp.async.wait_group 0;");
            }
            __syncthreads();
        }
    }

    // ---- epilogue: fp32 scale, round through fp16, store fp32 -----------
    const int col = n0 + warp * 8 + 2 * tg;
    float2 s2 = *(const float2*)(scale + col);
    #pragma unroll
    for (int mf = 0; mf < 2; mf++) {
        int r0 = mf * 16 + g;
        float2 o0, o1;
        o0.x = __half2float(__float2half_rn(acc[mf][0] * s2.x));
        o0.y = __half2float(__float2half_rn(acc[mf][1] * s2.y));
        o1.x = __half2float(__float2half_rn(acc[mf][2] * s2.x));
        o1.y = __half2float(__float2half_rn(acc[mf][3] * s2.y));
        *(float2*)(out + (size_t)r0 * NN + col) = o0;
        *(float2*)(out + (size_t)(r0 + 8) * NN + col) = o1;
    }
}

extern "C" void kernel_launch(void* const* d_in, const int* in_sizes, int n_in,
                              void* d_out, int out_size) {
    const float* act   = (const float*)d_in[0];
    const int*   w32   = (const int*)d_in[1];
    const float* scale = (const float*)d_in[2];
    float*       out   = (float*)d_out;

    cvt_act_kernel<<<(MM * KK / 2) / 256, 256>>>(act);

    cudaFuncSetAttribute(i8w_gemm_f32,
                         cudaFuncAttributeMaxDynamicSharedMemorySize,
                         SMEM_BYTES);
    i8w_gemm_f32<<<NN / N_TILE, 256, SMEM_BYTES>>>(w32, scale, out);
}

// round 12
// speedup vs baseline: 2.4443x; 2.4443x over previous
#include <cuda_runtime.h>
#include <cuda_fp16.h>
#include <cstdint>

#define MM 32
#define KK 8192
#define NN 28672
#define N_TILE 128
#define K_TILE 64
#define NK_ITERS (KK / K_TILE)            // 128
#define A_STRIDE 144                      // 64 halves (128B) + 16B pad
#define WT_STRIDE 544                     // 128 quad-u32 (512B) + 32B pad
#define WB_STRIDE (4 * WT_STRIDE)         // 2176B per k16 block
#define A_BYTES (MM * A_STRIDE)           // 4608
#define W_BYTES (4 * WB_STRIDE)           // 8704
#define STAGE_BYTES (A_BYTES + W_BYTES)   // 13312
#define SMEM_BYTES (2 * STAGE_BYTES)      // 26624

__device__ __half g_act16[MM * KK];       // 512KB scratch; L2-resident

__device__ __forceinline__ uint32_t prmt_(uint32_t a, uint32_t b, uint32_t s) {
    uint32_t d;
    asm("prmt.b32 %0,%1,%2,%3;" : "=r"(d) : "r"(a), "r"(b), "r"(s));
    return d;
}

__device__ __forceinline__ void mma16816(float* c, const uint32_t* a,
                                         uint32_t b0, uint32_t b1) {
    asm volatile(
        "mma.sync.aligned.m16n8k16.row.col.f32.f16.f16.f32 "
        "{%0,%1,%2,%3}, {%4,%5,%6,%7}, {%8,%9}, {%0,%1,%2,%3};"
        : "+f"(c[0]), "+f"(c[1]), "+f"(c[2]), "+f"(c[3])
        : "r"(a[0]), "r"(a[1]), "r"(a[2]), "r"(a[3]), "r"(b0), "r"(b1));
}

__device__ __forceinline__ void cp16(uint32_t dst_smem, const void* src) {
    asm volatile("cp.async.cg.shared.global [%0], [%1], 16;"
                 :: "r"(dst_smem), "l"(src));
}

// ---- pre-pass: act fp32 -> fp16 -------------------------------------------
__global__ void cvt_act_kernel(const float* __restrict__ act) {
    int i = blockIdx.x * blockDim.x + threadIdx.x;
    float2 v = ((const float2*)act)[i];
    ((__half2*)g_act16)[i] = __floats2half2_rn(v.x, v.y);
}

// ---- main GEMM -------------------------------------------------------------
__global__ void __launch_bounds__(256, 3)
i8w_gemm_f32(const int* __restrict__ w32,
             const float* __restrict__ scale,
             float* __restrict__ out) {
    extern __shared__ char smem[];
    const int tid  = threadIdx.x;
    const int warp = tid >> 5;
    const int lane = tid & 31;
    const int g  = lane >> 2;
    const int tg = lane & 3;
    const int n0 = blockIdx.x * N_TILE;
    const uint32_t smem_u = (uint32_t)__cvta_generic_to_shared(smem);

    // fetch assignment: thread owns k16 block fb, pair-slot ft, 8-n segment ns
    const int fb = tid >> 6;            // 0..3
    const int ft = (tid >> 4) & 3;      // 0..3
    const int ns = tid & 15;            // 0..15

    float acc[2][2][4];
    #pragma unroll
    for (int mf = 0; mf < 2; mf++)
        #pragma unroll
        for (int nf = 0; nf < 2; nf++)
            #pragma unroll
            for (int r = 0; r < 4; r++) acc[mf][nf][r] = 0.f;

    int4 rv[4][2];   // raw int32 weights: rows {2ft,2ft+1,2ft+8,2ft+9}, 8 n each

    auto fetchW = [&](int kt) {
        const int r0 = kt * K_TILE + fb * 16 + 2 * ft;
        const int nn = n0 + ns * 8;
        #pragma unroll
        for (int r = 0; r < 4; r++) {
            const int row = r0 + (r >> 1) * 8 + (r & 1);   // 2ft,2ft+1,2ft+8,2ft+9
            const int4* src = (const int4*)(w32 + (size_t)row * NN + nn);
            rv[r][0] = __ldg(src);
            rv[r][1] = __ldg(src + 1);
        }
    };

    // byte-transpose: for each n, quad u32 [b(r0),b(r1),b(r8),b(r9)]; 32B STS
    auto stageW = [&](int s) {
        char* dst = smem + s * STAGE_BYTES + A_BYTES
                  + fb * WB_STRIDE + ft * WT_STRIDE + ns * 32;
        uint32_t q[8];
        #pragma unroll
        for (int w = 0; w < 2; w++) {
            const uint32_t* e0 = (const uint32_t*)&rv[0][w];
            const uint32_t* e1 = (const uint32_t*)&rv[1][w];
            const uint32_t* e8 = (const uint32_t*)&rv[2][w];
            const uint32_t* e9 = (const uint32_t*)&rv[3][w];
            #pragma unroll
            for (int j = 0; j < 4; j++) {
                q[w * 4 + j] = prmt_(prmt_(e0[j], e1[j], 0x0040u),
                                     prmt_(e8[j], e9[j], 0x0040u), 0x5410u);
            }
        }
        *(uint4*)dst        = make_uint4(q[0], q[1], q[2], q[3]);
        *(uint4*)(dst + 16) = make_uint4(q[4], q[5], q[6], q[7]);
    };

    auto cpA = [&](int kt, int s) {
        const int row = tid >> 3, c8 = tid & 7;
        cp16(smem_u + s * STAGE_BYTES + row * A_STRIDE + c8 * 16,
             g_act16 + (size_t)row * KK + kt * K_TILE + c8 * 8);
        asm volatile("cp.async.commit_group;");
    };

    auto compute = [&](int s) {
        const uint32_t sA = smem_u + s * STAGE_BYTES;
        const char* Wp = smem + s * STAGE_BYTES + A_BYTES;
        #pragma unroll
        for (int b = 0; b < 4; b++) {
            const int kb = b * 16;
            uint32_t a[2][4];
            #pragma unroll
            for (int mf = 0; mf < 2; mf++) {
                uint32_t addr = sA + (mf * 16 + (lane & 15)) * A_STRIDE
                              + kb * 2 + (lane >> 4) * 16;
                asm volatile(
                    "ldmatrix.sync.aligned.m8n8.x4.shared.b16 {%0,%1,%2,%3}, [%4];"
                    : "=r"(a[mf][0]), "=r"(a[mf][1]),
                      "=r"(a[mf][2]), "=r"(a[mf][3])
                    : "r"(addr));
            }
            const char* wrow = Wp + b * WB_STRIDE + tg * WT_STRIDE;
            #pragma unroll
            for (int nf = 0; nf < 2; nf++) {
                uint32_t qd = *(const uint32_t*)
                    (wrow + (warp * 16 + nf * 8 + g) * 4);
                // exact int8->fp16: flip sign, splice 0x64 exponent, sub 1152
                uint32_t p = qd ^ 0x80808080u;
                uint32_t h0 = prmt_(p, 0x64646464u, 0x4140u);  // bytes 0,1
                uint32_t h1 = prmt_(p, 0x64646464u, 0x4342u);  // bytes 2,3
                uint32_t magic = 0x64806480u;                   // half2(1152,1152)
                __half2 m = *reinterpret_cast<__half2*>(&magic);
                __half2 f0 = __hsub2(*reinterpret_cast<__half2*>(&h0), m);
                __half2 f1 = __hsub2(*reinterpret_cast<__half2*>(&h1), m);
                uint32_t b0 = *reinterpret_cast<uint32_t*>(&f0);
                uint32_t b1 = *reinterpret_cast<uint32_t*>(&f1);
                mma16816(acc[0][nf], a[0], b0, b1);
                mma16816(acc[1][nf], a[1], b0, b1);
            }
        }
    };

    // ---- pipeline: distance-1 register stage for W, cp.async for A --------
    fetchW(0);
    cpA(0, 0);
    stageW(0);
    asm volatile("cp.async.wait_group 0;");
    __syncthreads();
    for (int kt = 0; kt < NK_ITERS; kt++) {
        const int s = kt & 1;
        if (kt + 1 < NK_ITERS) {
            fetchW(kt + 1);          // LDG latency hidden by compute below
            cpA(kt + 1, s ^ 1);      // s^1 free since previous sync
        }
        compute(s);
        __syncthreads();
        if (kt + 1 < NK_ITERS) {
            stageW(s ^ 1);
            asm volatile("cp.async.wait_group 0;");
            __syncthreads();
        }
    }

    // ---- epilogue: fp32 scale, round through fp16, store fp32 -------------
    #pragma unroll
    for (int nf = 0; nf < 2; nf++) {
        const int col = n0 + warp * 16 + nf * 8 + 2 * tg;
        float2 s2 = *(const float2*)(scale + col);
        #pragma unroll
        for (int mf = 0; mf < 2; mf++) {
            int r0 = mf * 16 + g;
            float2 o0, o1;
            o0.x = __half2float(__float2half_rn(acc[mf][nf][0] * s2.x));
            o0.y = __half2float(__float2half_rn(acc[mf][nf][1] * s2.y));
            o1.x = __half2float(__float2half_rn(acc[mf][nf][2] * s2.x));
            o1.y = __half2float(__float2half_rn(acc[mf][nf][3] * s2.y));
            *(float2*)(out + (size_t)r0 * NN + col) = o0;
            *(float2*)(out + (size_t)(r0 + 8) * NN + col) = o1;
        }
    }
}

extern "C" void kernel_launch(void* const* d_in, const int* in_sizes, int n_in,
                              void* d_out, int out_size) {
    const float* act   = (const float*)d_in[0];
    const int*   w32   = (const int*)d_in[1];
    const float* scale = (const float*)d_in[2];
    float*       out   = (float*)d_out;

    cvt_act_kernel<<<(MM * KK / 2) / 256, 256>>>(act);

    cudaFuncSetAttribute(i8w_gemm_f32,
                         cudaFuncAttributeMaxDynamicSharedMemorySize,
                         SMEM_BYTES);
    i8w_gemm_f32<<<NN / N_TILE, 256, SMEM_BYTES>>>(w32, scale, out);
}

// round 15
// speedup vs baseline: 2.9160x; 1.1930x over previous
#include <cuda_runtime.h>
#include <cuda_fp16.h>
#include <cstdint>

#define MM 32
#define KK 8192
#define NN 28672
#define N_TILE 128
#define K_TILE 64
#define KSPLIT 2
#define NK_ITERS (KK / KSPLIT / K_TILE)   // 64 per CTA
#define A_STRIDE 144                      // 64 halves (128B) + 16B pad
#define WT_STRIDE 544                     // 128 quad-u32 (512B) + 32B pad
#define WB_STRIDE (4 * WT_STRIDE)         // 2176B per k16 block
#define A_BYTES (MM * A_STRIDE)           // 4608
#define W_BYTES (4 * WB_STRIDE)           // 8704
#define STAGE_BYTES (A_BYTES + W_BYTES)   // 13312
#define SMEM_BYTES (2 * STAGE_BYTES)      // 26624

__device__ __half g_act16[MM * KK];          // 512KB, L2-resident
__device__ float  g_part[KSPLIT][MM * NN];   // 7.3MB fp32 partials

__device__ __forceinline__ uint32_t prmt_(uint32_t a, uint32_t b, uint32_t s) {
    uint32_t d;
    asm("prmt.b32 %0,%1,%2,%3;" : "=r"(d) : "r"(a), "r"(b), "r"(s));
    return d;
}

__device__ __forceinline__ void mma16816(float* c, const uint32_t* a,
                                         uint32_t b0, uint32_t b1) {
    asm volatile(
        "mma.sync.aligned.m16n8k16.row.col.f32.f16.f16.f32 "
        "{%0,%1,%2,%3}, {%4,%5,%6,%7}, {%8,%9}, {%0,%1,%2,%3};"
        : "+f"(c[0]), "+f"(c[1]), "+f"(c[2]), "+f"(c[3])
        : "r"(a[0]), "r"(a[1]), "r"(a[2]), "r"(a[3]), "r"(b0), "r"(b1));
}

__device__ __forceinline__ void cp16(uint32_t dst_smem, const void* src) {
    asm volatile("cp.async.cg.shared.global [%0], [%1], 16;"
                 :: "r"(dst_smem), "l"(src));
}

// ---- pre-pass: act fp32 -> fp16 -------------------------------------------
__global__ void cvt_act_kernel(const float* __restrict__ act) {
    int i = blockIdx.x * blockDim.x + threadIdx.x;
    float2 v = ((const float2*)act)[i];
    ((__half2*)g_act16)[i] = __floats2half2_rn(v.x, v.y);
}

// ---- main GEMM: one CTA = (n-tile, k-half), writes fp32 partials -----------
__global__ void __launch_bounds__(256, 3)
i8w_gemm_f32(const int* __restrict__ w32) {
    extern __shared__ char smem[];
    const int tid  = threadIdx.x;
    const int warp = tid >> 5;
    const int lane = tid & 31;
    const int g  = lane >> 2;
    const int tg = lane & 3;
    const int n0    = (blockIdx.x >> 1) * N_TILE;
    const int khalf = blockIdx.x & 1;
    const int kbase = khalf * (KK / KSPLIT);
    const uint32_t smem_u = (uint32_t)__cvta_generic_to_shared(smem);

    // fetch assignment: thread owns k16 block fb, pair-slot ft, 8-n segment ns
    const int fb = tid >> 6;            // 0..3
    const int ft = (tid >> 4) & 3;      // 0..3
    const int ns = tid & 15;            // 0..15

    float acc[2][2][4];
    #pragma unroll
    for (int mf = 0; mf < 2; mf++)
        #pragma unroll
        for (int nf = 0; nf < 2; nf++)
            #pragma unroll
            for (int r = 0; r < 4; r++) acc[mf][nf][r] = 0.f;

    int4 rv[4][2];   // raw int32 weights: rows {2ft,2ft+1,2ft+8,2ft+9}, 8 n each

    auto fetchW = [&](int kt) {
        const int r0 = kbase + kt * K_TILE + fb * 16 + 2 * ft;
        const int nn = n0 + ns * 8;
        #pragma unroll
        for (int r = 0; r < 4; r++) {
            const int row = r0 + (r >> 1) * 8 + (r & 1);
            const int4* src = (const int4*)(w32 + (size_t)row * NN + nn);
            rv[r][0] = __ldg(src);
            rv[r][1] = __ldg(src + 1);
        }
    };

    // byte-transpose: per n, quad u32 [b(r0),b(r1),b(r8),b(r9)]; 32B STS
    auto stageW = [&](int s) {
        char* dst = smem + s * STAGE_BYTES + A_BYTES
                  + fb * WB_STRIDE + ft * WT_STRIDE + ns * 32;
        uint32_t q[8];
        #pragma unroll
        for (int w = 0; w < 2; w++) {
            const uint32_t* e0 = (const uint32_t*)&rv[0][w];
            const uint32_t* e1 = (const uint32_t*)&rv[1][w];
            const uint32_t* e8 = (const uint32_t*)&rv[2][w];
            const uint32_t* e9 = (const uint32_t*)&rv[3][w];
            #pragma unroll
            for (int j = 0; j < 4; j++) {
                q[w * 4 + j] = prmt_(prmt_(e0[j], e1[j], 0x0040u),
                                     prmt_(e8[j], e9[j], 0x0040u), 0x5410u);
            }
        }
        *(uint4*)dst        = make_uint4(q[0], q[1], q[2], q[3]);
        *(uint4*)(dst + 16) = make_uint4(q[4], q[5], q[6], q[7]);
    };

    auto cpA = [&](int kt, int s) {
        const int row = tid >> 3, c8 = tid & 7;
        cp16(smem_u + s * STAGE_BYTES + row * A_STRIDE + c8 * 16,
             g_act16 + (size_t)row * KK + kbase + kt * K_TILE + c8 * 8);
        asm volatile("cp.async.commit_group;");
    };

    auto compute = [&](int s) {
        const uint32_t sA = smem_u + s * STAGE_BYTES;
        const char* Wp = smem + s * STAGE_BYTES + A_BYTES;
        #pragma unroll
        for (int b = 0; b < 4; b++) {
            const int kb = b * 16;
            uint32_t a[2][4];
            #pragma unroll
            for (int mf = 0; mf < 2; mf++) {
                uint32_t addr = sA + (mf * 16 + (lane & 15)) * A_STRIDE
                              + kb * 2 + (lane >> 4) * 16;
                asm volatile(
                    "ldmatrix.sync.aligned.m8n8.x4.shared.b16 {%0,%1,%2,%3}, [%4];"
                    : "=r"(a[mf][0]), "=r"(a[mf][1]),
                      "=r"(a[mf][2]), "=r"(a[mf][3])
                    : "r"(addr));
            }
            const char* wrow = Wp + b * WB_STRIDE + tg * WT_STRIDE;
            #pragma unroll
            for (int nf = 0; nf < 2; nf++) {
                uint32_t qd = *(const uint32_t*)
                    (wrow + (warp * 16 + nf * 8 + g) * 4);
                // exact int8->fp16: flip sign, splice 0x64 exponent, sub 1152
                uint32_t p = qd ^ 0x80808080u;
                uint32_t h0 = prmt_(p, 0x64646464u, 0x4140u);
                uint32_t h1 = prmt_(p, 0x64646464u, 0x4342u);
                uint32_t magic = 0x64806480u;
                __half2 m = *reinterpret_cast<__half2*>(&magic);
                __half2 f0 = __hsub2(*reinterpret_cast<__half2*>(&h0), m);
                __half2 f1 = __hsub2(*reinterpret_cast<__half2*>(&h1), m);
                uint32_t b0 = *reinterpret_cast<uint32_t*>(&f0);
                uint32_t b1 = *reinterpret_cast<uint32_t*>(&f1);
                mma16816(acc[0][nf], a[0], b0, b1);
                mma16816(acc[1][nf], a[1], b0, b1);
            }
        }
    };

    // ---- pipeline: distance-1 register stage for W, cp.async for A --------
    fetchW(0);
    cpA(0, 0);
    stageW(0);
    asm volatile("cp.async.wait_group 0;");
    __syncthreads();
    for (int kt = 0; kt < NK_ITERS; kt++) {
        const int s = kt & 1;
        if (kt + 1 < NK_ITERS) {
            fetchW(kt + 1);
            cpA(kt + 1, s ^ 1);
        }
        compute(s);
        __syncthreads();
        if (kt + 1 < NK_ITERS) {
            stageW(s ^ 1);
            asm volatile("cp.async.wait_group 0;");
            __syncthreads();
        }
    }

    // ---- store unscaled fp32 partials -------------------------------------
    float* dst = g_part[khalf];
    #pragma unroll
    for (int nf = 0; nf < 2; nf++) {
        const int col = n0 + warp * 16 + nf * 8 + 2 * tg;
        #pragma unroll
        for (int mf = 0; mf < 2; mf++) {
            int r0 = mf * 16 + g;
            *(float2*)(dst + (size_t)r0 * NN + col) =
                make_float2(acc[mf][nf][0], acc[mf][nf][1]);
            *(float2*)(dst + (size_t)(r0 + 8) * NN + col) =
                make_float2(acc[mf][nf][2], acc[mf][nf][3]);
        }
    }
}

// ---- reduction + scale + fp16 rounding, fp32 out ---------------------------
__global__ void reduce_kernel(const float* __restrict__ scale,
                              float* __restrict__ out) {
    int i = blockIdx.x * blockDim.x + threadIdx.x;   // float4 index
    float4 p0 = ((const float4*)g_part[0])[i];
    float4 p1 = ((const float4*)g_part[1])[i];
    int col = (i * 4) % NN;
    float4 s = *(const float4*)(scale + col);
    float4 o;
    o.x = __half2float(__float2half_rn((p0.x + p1.x) * s.x));
    o.y = __half2float(__float2half_rn((p0.y + p1.y) * s.y));
    o.z = __half2float(__float2half_rn((p0.z + p1.z) * s.z));
    o.w = __half2float(__float2half_rn((p0.w + p1.w) * s.w));
    ((float4*)out)[i] = o;
}

extern "C" void kernel_launch(void* const* d_in, const int* in_sizes, int n_in,
                              void* d_out, int out_size) {
    const float* act   = (const float*)d_in[0];
    const int*   w32   = (const int*)d_in[1];
    const float* scale = (const float*)d_in[2];
    float*       out   = (float*)d_out;

    cvt_act_kernel<<<(MM * KK / 2) / 256, 256>>>(act);

    cudaFuncSetAttribute(i8w_gemm_f32,
                         cudaFuncAttributeMaxDynamicSharedMemorySize,
                         SMEM_BYTES);
    i8w_gemm_f32<<<(NN / N_TILE) * KSPLIT, 256, SMEM_BYTES>>>(w32);

    reduce_kernel<<<(MM * NN / 4) / 256, 256>>>(scale, out);
}

// round 16
// speedup vs baseline: 2.9198x; 1.0013x over previous
#include <cuda_runtime.h>
#include <cuda_fp16.h>
#include <cstdint>

#define MM 32
#define KK 8192
#define NN 28672
#define N_TILE 128
#define K_TILE 64
#define KSPLIT 2
#define NTILES (NN / N_TILE)              // 224
#define NK_ITERS (KK / KSPLIT / K_TILE)   // 64 per CTA
#define A_STRIDE 144                      // 64 halves (128B) + 16B pad
#define WT_STRIDE 544                     // 128 quad-u32 (512B) + 32B pad
#define WB_STRIDE (4 * WT_STRIDE)         // 2176B per k16 block
#define A_BYTES (MM * A_STRIDE)           // 4608
#define W_BYTES (4 * WB_STRIDE)           // 8704
#define STAGE_BYTES (A_BYTES + W_BYTES)   // 13312
#define SMEM_BYTES (2 * STAGE_BYTES)      // 26624

__device__ __half g_act16[MM * KK];       // 512KB, L2-resident
__device__ float  g_part[MM * NN];        // 3.67MB fp32 partials (khalf 0)
__device__ int    g_flag[NTILES];         // per-tile release flags

__device__ __forceinline__ uint32_t prmt_(uint32_t a, uint32_t b, uint32_t s) {
    uint32_t d;
    asm("prmt.b32 %0,%1,%2,%3;" : "=r"(d) : "r"(a), "r"(b), "r"(s));
    return d;
}

__device__ __forceinline__ void mma16816(float* c, const uint32_t* a,
                                         uint32_t b0, uint32_t b1) {
    asm volatile(
        "mma.sync.aligned.m16n8k16.row.col.f32.f16.f16.f32 "
        "{%0,%1,%2,%3}, {%4,%5,%6,%7}, {%8,%9}, {%0,%1,%2,%3};"
        : "+f"(c[0]), "+f"(c[1]), "+f"(c[2]), "+f"(c[3])
        : "r"(a[0]), "r"(a[1]), "r"(a[2]), "r"(a[3]), "r"(b0), "r"(b1));
}

__device__ __forceinline__ void cp16(uint32_t dst_smem, const void* src) {
    asm volatile("cp.async.cg.shared.global [%0], [%1], 16;"
                 :: "r"(dst_smem), "l"(src));
}

// ---- pre-pass: act fp32 -> fp16, plus flag reset (stream-ordered) ----------
__global__ void cvt_act_kernel(const float* __restrict__ act) {
    int i = blockIdx.x * blockDim.x + threadIdx.x;
    if (i < NTILES) g_flag[i] = 0;
    float2 v = ((const float2*)act)[i];
    ((__half2*)g_act16)[i] = __floats2half2_rn(v.x, v.y);
}

// ---- main GEMM: one CTA = (n-tile, k-half); fused pairwise reduction -------
__global__ void __launch_bounds__(256, 3)
i8w_gemm_f32(const int* __restrict__ w32,
             const float* __restrict__ scale,
             float* __restrict__ out) {
    extern __shared__ char smem[];
    const int tid  = threadIdx.x;
    const int warp = tid >> 5;
    const int lane = tid & 31;
    const int g  = lane >> 2;
    const int tg = lane & 3;
    const int tile  = blockIdx.x >> 1;
    const int n0    = tile * N_TILE;
    const int khalf = blockIdx.x & 1;
    const int kbase = khalf * (KK / KSPLIT);
    const uint32_t smem_u = (uint32_t)__cvta_generic_to_shared(smem);

    // fetch assignment: thread owns k16 block fb, pair-slot ft, 8-n segment ns
    const int fb = tid >> 6;            // 0..3
    const int ft = (tid >> 4) & 3;      // 0..3
    const int ns = tid & 15;            // 0..15

    float acc[2][2][4];
    #pragma unroll
    for (int mf = 0; mf < 2; mf++)
        #pragma unroll
        for (int nf = 0; nf < 2; nf++)
            #pragma unroll
            for (int r = 0; r < 4; r++) acc[mf][nf][r] = 0.f;

    int4 rv[4][2];   // raw int32 weights: rows {2ft,2ft+1,2ft+8,2ft+9}, 8 n each

    auto fetchW = [&](int kt) {
        const int r0 = kbase + kt * K_TILE + fb * 16 + 2 * ft;
        const int nn = n0 + ns * 8;
        #pragma unroll
        for (int r = 0; r < 4; r++) {
            const int row = r0 + (r >> 1) * 8 + (r & 1);
            const int4* src = (const int4*)(w32 + (size_t)row * NN + nn);
            rv[r][0] = __ldg(src);
            rv[r][1] = __ldg(src + 1);
        }
    };

    // byte-transpose: per n, quad u32 [b(r0),b(r1),b(r8),b(r9)]; 32B STS
    auto stageW = [&](int s) {
        char* dst = smem + s * STAGE_BYTES + A_BYTES
                  + fb * WB_STRIDE + ft * WT_STRIDE + ns * 32;
        uint32_t q[8];
        #pragma unroll
        for (int w = 0; w < 2; w++) {
            const uint32_t* e0 = (const uint32_t*)&rv[0][w];
            const uint32_t* e1 = (const uint32_t*)&rv[1][w];
            const uint32_t* e8 = (const uint32_t*)&rv[2][w];
            const uint32_t* e9 = (const uint32_t*)&rv[3][w];
            #pragma unroll
            for (int j = 0; j < 4; j++) {
                q[w * 4 + j] = prmt_(prmt_(e0[j], e1[j], 0x0040u),
                                     prmt_(e8[j], e9[j], 0x0040u), 0x5410u);
            }
        }
        *(uint4*)dst        = make_uint4(q[0], q[1], q[2], q[3]);
        *(uint4*)(dst + 16) = make_uint4(q[4], q[5], q[6], q[7]);
    };

    auto cpA = [&](int kt, int s) {
        const int row = tid >> 3, c8 = tid & 7;
        cp16(smem_u + s * STAGE_BYTES + row * A_STRIDE + c8 * 16,
             g_act16 + (size_t)row * KK + kbase + kt * K_TILE + c8 * 8);
        asm volatile("cp.async.commit_group;");
    };

    auto compute = [&](int s) {
        const uint32_t sA = smem_u + s * STAGE_BYTES;
        const char* Wp = smem + s * STAGE_BYTES + A_BYTES;
        #pragma unroll
        for (int b = 0; b < 4; b++) {
            const int kb = b * 16;
            uint32_t a[2][4];
            #pragma unroll
            for (int mf = 0; mf < 2; mf++) {
                uint32_t addr = sA + (mf * 16 + (lane & 15)) * A_STRIDE
                              + kb * 2 + (lane >> 4) * 16;
                asm volatile(
                    "ldmatrix.sync.aligned.m8n8.x4.shared.b16 {%0,%1,%2,%3}, [%4];"
                    : "=r"(a[mf][0]), "=r"(a[mf][1]),
                      "=r"(a[mf][2]), "=r"(a[mf][3])
                    : "r"(addr));
            }
            const char* wrow = Wp + b * WB_STRIDE + tg * WT_STRIDE;
            #pragma unroll
            for (int nf = 0; nf < 2; nf++) {
                uint32_t qd = *(const uint32_t*)
                    (wrow + (warp * 16 + nf * 8 + g) * 4);
                // exact int8->fp16: flip sign, splice 0x64 exponent, sub 1152
                uint32_t p = qd ^ 0x80808080u;
                uint32_t h0 = prmt_(p, 0x64646464u, 0x4140u);
                uint32_t h1 = prmt_(p, 0x64646464u, 0x4342u);
                uint32_t magic = 0x64806480u;
                __half2 m = *reinterpret_cast<__half2*>(&magic);
                __half2 f0 = __hsub2(*reinterpret_cast<__half2*>(&h0), m);
                __half2 f1 = __hsub2(*reinterpret_cast<__half2*>(&h1), m);
                uint32_t b0 = *reinterpret_cast<uint32_t*>(&f0);
                uint32_t b1 = *reinterpret_cast<uint32_t*>(&f1);
                mma16816(acc[0][nf], a[0], b0, b1);
                mma16816(acc[1][nf], a[1], b0, b1);
            }
        }
    };

    // ---- pipeline: ONE barrier per iteration ------------------------------
    // Hazards: stageW writes s^1 while compute reads s (disjoint); cpA writes
    // A(s^1) whose last reader finished before the PREVIOUS barrier.
    fetchW(0);
    cpA(0, 0);
    stageW(0);
    asm volatile("cp.async.wait_group 0;");
    __syncthreads();
    for (int kt = 0; kt < NK_ITERS; kt++) {
        const int s = kt & 1;
        if (kt + 1 < NK_ITERS) {
            fetchW(kt + 1);
            cpA(kt + 1, s ^ 1);
        }
        compute(s);
        if (kt + 1 < NK_ITERS) {
            stageW(s ^ 1);
            asm volatile("cp.async.wait_group 0;");
        }
        __syncthreads();
    }

    // ---- fused pairwise reduction -----------------------------------------
    if (khalf == 0) {
        // store unscaled fp32 partials, then release the tile flag
        #pragma unroll
        for (int nf = 0; nf < 2; nf++) {
            const int col = n0 + warp * 16 + nf * 8 + 2 * tg;
            #pragma unroll
            for (int mf = 0; mf < 2; mf++) {
                int r0 = mf * 16 + g;
                *(float2*)(g_part + (size_t)r0 * NN + col) =
                    make_float2(acc[mf][nf][0], acc[mf][nf][1]);
                *(float2*)(g_part + (size_t)(r0 + 8) * NN + col) =
                    make_float2(acc[mf][nf][2], acc[mf][nf][3]);
            }
        }
        __threadfence();
        __syncthreads();
        if (tid == 0) {
            asm volatile("st.global.release.gpu.b32 [%0], %1;"
                         :: "l"(g_flag + tile), "r"(1) : "memory");
        }
    } else {
        // acquire partner's partials, then add + scale + fp16-round + store
        if (tid == 0) {
            int f;
            do {
                asm volatile("ld.global.acquire.gpu.b32 %0, [%1];"
                             : "=r"(f) : "l"(g_flag + tile) : "memory");
                if (!f) __nanosleep(64);
            } while (!f);
        }
        __syncthreads();
        #pragma unroll
        for (int nf = 0; nf < 2; nf++) {
            const int col = n0 + warp * 16 + nf * 8 + 2 * tg;
            float2 s2 = *(const float2*)(scale + col);
            #pragma unroll
            for (int mf = 0; mf < 2; mf++) {
                int r0 = mf * 16 + g;
                float2 p0 = *(const float2*)(g_part + (size_t)r0 * NN + col);
                float2 p1 = *(const float2*)(g_part + (size_t)(r0 + 8) * NN + col);
                float2 o0, o1;
                o0.x = __half2float(__float2half_rn((p0.x + acc[mf][nf][0]) * s2.x));
                o0.y = __half2float(__float2half_rn((p0.y + acc[mf][nf][1]) * s2.y));
                o1.x = __half2float(__float2half_rn((p1.x + acc[mf][nf][2]) * s2.x));
                o1.y = __half2float(__float2half_rn((p1.y + acc[mf][nf][3]) * s2.y));
                *(float2*)(out + (size_t)r0 * NN + col) = o0;
                *(float2*)(out + (size_t)(r0 + 8) * NN + col) = o1;
            }
        }
    }
}

extern "C" void kernel_launch(void* const* d_in, const int* in_sizes, int n_in,
                              void* d_out, int out_size) {
    const float* act   = (const float*)d_in[0];
    const int*   w32   = (const int*)d_in[1];
    const float* scale = (const float*)d_in[2];
    float*       out   = (float*)d_out;

    cvt_act_kernel<<<(MM * KK / 2) / 256, 256>>>(act);

    cudaFuncSetAttribute(i8w_gemm_f32,
                         cudaFuncAttributeMaxDynamicSharedMemorySize,
                         SMEM_BYTES);
    i8w_gemm_f32<<<NTILES * KSPLIT, 256, SMEM_BYTES>>>(w32, scale, out);
}